// round 4
// baseline (speedup 1.0000x reference)
#include <cuda_runtime.h>
#include <cuda_bf16.h>

// Problem: B=4, N=4096 (keys=queries), D=64, H=256.
// out[b,q,dv] = (softmax_k( -0.5*cdistL1(Ks,Qs)^2 ) @ V) * Wo
//   Ks = KEY*mlp(KEY), Qs = QUERY*mlp(QUERY), Wo = mlpo(QUERY)
// L1 dist(k,q) = sk[k] + sq[q] - 2*sum_d min(Ks,Qs); flash softmax tracks min score.

#define NB   4
#define NSEQ 4096
#define DD   64
#define NROWS (NB * NSEQ)

// scratch (no allocation allowed -> device globals)
__device__ float g_Ks[NROWS * DD];
__device__ float g_Qs[NROWS * DD];
__device__ float g_Wo[NROWS * DD];
__device__ float g_sk[NROWS];
__device__ float g_sq[NROWS];

// ---- packed fp32x2 helpers (Blackwell FADD2/FFMA2, only reachable via PTX) ----
__device__ __forceinline__ void addx2(float& ax, float& ay, float bx, float by) {
    asm("{\n\t.reg .b64 ra, rb;\n\t"
        "mov.b64 ra, {%0, %1};\n\t"
        "mov.b64 rb, {%2, %3};\n\t"
        "add.rn.f32x2 ra, ra, rb;\n\t"
        "mov.b64 {%0, %1}, ra;\n\t}"
        : "+f"(ax), "+f"(ay) : "f"(bx), "f"(by));
}
__device__ __forceinline__ void fmax2(float& cx, float& cy, float ax, float ay,
                                      float bx, float by) {
    asm("{\n\t.reg .b64 rc, ra, rb;\n\t"
        "mov.b64 rc, {%0, %1};\n\t"
        "mov.b64 ra, {%2, %3};\n\t"
        "mov.b64 rb, {%4, %5};\n\t"
        "fma.rn.f32x2 rc, ra, rb, rc;\n\t"
        "mov.b64 {%0, %1}, rc;\n\t}"
        : "+f"(cx), "+f"(cy) : "f"(ax), "f"(ay), "f"(bx), "f"(by));
}
// force a physically distinct register copy (for {a,a} operand pairing)
__device__ __forceinline__ float dupreg(float x) {
    float y;
    asm volatile("mov.f32 %0, %1;" : "=f"(y) : "f"(x));
    return y;
}

// ---------------------------------------------------------------------------
// MLP kernel. One block = 32 rows. mode(blockIdx.y): 0 KEY->Ks,sk ;
// 1 QUERY->Qs,sq ; 2 QUERY->Wo. Layers 64 ->256 relu -> 256 relu -> 64.
// ---------------------------------------------------------------------------
#define MLP_SMEM_FLOATS (32*68 + 32*260 + 32*260 + 64*260)

__global__ void __launch_bounds__(256, 1) mlp_kernel(
    const float* __restrict__ KEY, const float* __restrict__ QUERY,
    const float* __restrict__ W1,  const float* __restrict__ B1,
    const float* __restrict__ W2,  const float* __restrict__ B2,
    const float* __restrict__ W3,  const float* __restrict__ B3,
    const float* __restrict__ W1o, const float* __restrict__ B1o,
    const float* __restrict__ W2o, const float* __restrict__ B2o,
    const float* __restrict__ W3o, const float* __restrict__ B3o)
{
    extern __shared__ float sm[];
    float* s_x = sm;              // 32*68
    float* s_a = s_x + 32 * 68;   // 32*260
    float* s_b = s_a + 32 * 260;  // 32*260
    float* s_w = s_b + 32 * 260;  // 64*260 (transposed weight chunk [in][out])

    const int t    = threadIdx.x;
    const int mode = blockIdx.y;
    const int row0 = blockIdx.x * 32;

    const float* X  = (mode == 0) ? KEY : QUERY;
    const float* w1 = (mode < 2) ? W1 : W1o;
    const float* b1 = (mode < 2) ? B1 : B1o;
    const float* w2 = (mode < 2) ? W2 : W2o;
    const float* b2 = (mode < 2) ? B2 : B2o;
    const float* w3 = (mode < 2) ? W3 : W3o;
    const float* b3 = (mode < 2) ? B3 : B3o;

    // input tile 32x64
    for (int idx = t; idx < 32 * 16; idx += 256) {
        int r = idx >> 4, c = (idx & 15) * 4;
        *(float4*)(s_x + r * 68 + c) =
            *(const float4*)(X + (size_t)(row0 + r) * 64 + c);
    }
    // stage W1 (256x64) transposed
    for (int idx = t; idx < 256 * 64; idx += 256) {
        int o = idx >> 6, i = idx & 63;
        s_w[i * 260 + o] = w1[idx];
    }
    __syncthreads();

    const int og = t & 31;   // 32 out-groups of 8
    const int rg = t >> 5;   // 8 row-groups of 4

    // ================= Layer 1: 64 -> 256, relu -> s_a =================
    {
        float acc[4][8];
#pragma unroll
        for (int r = 0; r < 4; r++)
#pragma unroll
            for (int c = 0; c < 8; c++) acc[r][c] = 0.f;

#pragma unroll 4
        for (int i = 0; i < 64; i++) {
            float a0 = s_x[(rg * 4 + 0) * 68 + i];
            float a1 = s_x[(rg * 4 + 1) * 68 + i];
            float a2 = s_x[(rg * 4 + 2) * 68 + i];
            float a3 = s_x[(rg * 4 + 3) * 68 + i];
            float a0d = dupreg(a0), a1d = dupreg(a1), a2d = dupreg(a2), a3d = dupreg(a3);
            float4 wA = *(const float4*)(s_w + i * 260 + og * 8);
            float4 wB = *(const float4*)(s_w + i * 260 + og * 8 + 4);
            fmax2(acc[0][0], acc[0][1], a0, a0d, wA.x, wA.y);
            fmax2(acc[0][2], acc[0][3], a0, a0d, wA.z, wA.w);
            fmax2(acc[0][4], acc[0][5], a0, a0d, wB.x, wB.y);
            fmax2(acc[0][6], acc[0][7], a0, a0d, wB.z, wB.w);
            fmax2(acc[1][0], acc[1][1], a1, a1d, wA.x, wA.y);
            fmax2(acc[1][2], acc[1][3], a1, a1d, wA.z, wA.w);
            fmax2(acc[1][4], acc[1][5], a1, a1d, wB.x, wB.y);
            fmax2(acc[1][6], acc[1][7], a1, a1d, wB.z, wB.w);
            fmax2(acc[2][0], acc[2][1], a2, a2d, wA.x, wA.y);
            fmax2(acc[2][2], acc[2][3], a2, a2d, wA.z, wA.w);
            fmax2(acc[2][4], acc[2][5], a2, a2d, wB.x, wB.y);
            fmax2(acc[2][6], acc[2][7], a2, a2d, wB.z, wB.w);
            fmax2(acc[3][0], acc[3][1], a3, a3d, wA.x, wA.y);
            fmax2(acc[3][2], acc[3][3], a3, a3d, wA.z, wA.w);
            fmax2(acc[3][4], acc[3][5], a3, a3d, wB.x, wB.y);
            fmax2(acc[3][6], acc[3][7], a3, a3d, wB.z, wB.w);
        }
#pragma unroll
        for (int c = 0; c < 8; c++) {
            int o = og * 8 + c;
            float bv = __ldg(b1 + o);
#pragma unroll
            for (int r = 0; r < 4; r++)
                s_a[(rg * 4 + r) * 260 + o] = fmaxf(acc[r][c] + bv, 0.f);
        }
    }

    // ================= Layer 2: 256 -> 256, relu -> s_b =================
    {
        float acc[4][8];
#pragma unroll
        for (int r = 0; r < 4; r++)
#pragma unroll
            for (int c = 0; c < 8; c++) acc[r][c] = 0.f;

        for (int ch = 0; ch < 4; ch++) {
            __syncthreads();
            for (int idx = t; idx < 256 * 64; idx += 256) {
                int o = idx >> 6, i = idx & 63;
                s_w[i * 260 + o] = w2[o * 256 + ch * 64 + i];
            }
            __syncthreads();
#pragma unroll 4
            for (int i = 0; i < 64; i++) {
                float a0 = s_a[(rg * 4 + 0) * 260 + ch * 64 + i];
                float a1 = s_a[(rg * 4 + 1) * 260 + ch * 64 + i];
                float a2 = s_a[(rg * 4 + 2) * 260 + ch * 64 + i];
                float a3 = s_a[(rg * 4 + 3) * 260 + ch * 64 + i];
                float a0d = dupreg(a0), a1d = dupreg(a1), a2d = dupreg(a2), a3d = dupreg(a3);
                float4 wA = *(const float4*)(s_w + i * 260 + og * 8);
                float4 wB = *(const float4*)(s_w + i * 260 + og * 8 + 4);
                fmax2(acc[0][0], acc[0][1], a0, a0d, wA.x, wA.y);
                fmax2(acc[0][2], acc[0][3], a0, a0d, wA.z, wA.w);
                fmax2(acc[0][4], acc[0][5], a0, a0d, wB.x, wB.y);
                fmax2(acc[0][6], acc[0][7], a0, a0d, wB.z, wB.w);
                fmax2(acc[1][0], acc[1][1], a1, a1d, wA.x, wA.y);
                fmax2(acc[1][2], acc[1][3], a1, a1d, wA.z, wA.w);
                fmax2(acc[1][4], acc[1][5], a1, a1d, wB.x, wB.y);
                fmax2(acc[1][6], acc[1][7], a1, a1d, wB.z, wB.w);
                fmax2(acc[2][0], acc[2][1], a2, a2d, wA.x, wA.y);
                fmax2(acc[2][2], acc[2][3], a2, a2d, wA.z, wA.w);
                fmax2(acc[2][4], acc[2][5], a2, a2d, wB.x, wB.y);
                fmax2(acc[2][6], acc[2][7], a2, a2d, wB.z, wB.w);
                fmax2(acc[3][0], acc[3][1], a3, a3d, wA.x, wA.y);
                fmax2(acc[3][2], acc[3][3], a3, a3d, wA.z, wA.w);
                fmax2(acc[3][4], acc[3][5], a3, a3d, wB.x, wB.y);
                fmax2(acc[3][6], acc[3][7], a3, a3d, wB.z, wB.w);
            }
        }
#pragma unroll
        for (int c = 0; c < 8; c++) {
            int o = og * 8 + c;
            float bv = __ldg(b2 + o);
#pragma unroll
            for (int r = 0; r < 4; r++)
                s_b[(rg * 4 + r) * 260 + o] = fmaxf(acc[r][c] + bv, 0.f);
        }
    }

    // ================= Layer 3: 256 -> 64 + epilogue =================
    {
        const int row = t >> 3;   // 32 rows, 8 threads each
        const int o8  = t & 7;    // 8 out-groups of 8
        float acc3[8];
#pragma unroll
        for (int c = 0; c < 8; c++) acc3[c] = 0.f;

        for (int ch = 0; ch < 4; ch++) {
            __syncthreads();
            for (int idx = t; idx < 64 * 64; idx += 256) {
                int o = idx >> 6, i = idx & 63;
                s_w[i * 260 + o] = w3[o * 256 + ch * 64 + i];
            }
            __syncthreads();
#pragma unroll 4
            for (int i = 0; i < 64; i++) {
                float a = s_b[row * 260 + ch * 64 + i];
                float4 wA = *(const float4*)(s_w + i * 260 + o8 * 8);
                float4 wB = *(const float4*)(s_w + i * 260 + o8 * 8 + 4);
                acc3[0] += a * wA.x; acc3[1] += a * wA.y;
                acc3[2] += a * wA.z; acc3[3] += a * wA.w;
                acc3[4] += a * wB.x; acc3[5] += a * wB.y;
                acc3[6] += a * wB.z; acc3[7] += a * wB.w;
            }
        }

        float val[8];
        float sum = 0.f;
#pragma unroll
        for (int c = 0; c < 8; c++) {
            int o = o8 * 8 + c;
            float y = acc3[c] + __ldg(b3 + o);
            if (mode < 2) { val[c] = y * s_x[row * 68 + o]; sum += val[c]; }
            else          { val[c] = y; }
        }
        float* dst = (mode == 0) ? g_Ks : (mode == 1) ? g_Qs : g_Wo;
        size_t grow = (size_t)(row0 + row);
        *(float4*)(dst + grow * 64 + o8 * 8)     = make_float4(val[0], val[1], val[2], val[3]);
        *(float4*)(dst + grow * 64 + o8 * 8 + 4) = make_float4(val[4], val[5], val[6], val[7]);
        if (mode < 2) {
            sum += __shfl_xor_sync(0xffffffffu, sum, 1);
            sum += __shfl_xor_sync(0xffffffffu, sum, 2);
            sum += __shfl_xor_sync(0xffffffffu, sum, 4);
            if (o8 == 0) ((mode == 0) ? g_sk : g_sq)[grow] = sum;
        }
    }
}

// ---------------------------------------------------------------------------
// Attention. Block = 64 queries (8 warps x 8 q), key chunks of 64.
// Lane owns 2 keys for scores, dv pair {2*lane,2*lane+1} for AV.
// p stored DUPLICATED ({p,p}) so AV's packed multiplier is one broadcast LDS.64.
// ---------------------------------------------------------------------------
#define ATT_SMEM_FLOATS (64*68 + 64*66 + 64*68 + 64*138 + 64)

__global__ void __launch_bounds__(256, 2) attn_kernel(
    const float* __restrict__ V, float* __restrict__ out)
{
    extern __shared__ float sm[];
    float* s_q  = sm;               // [64][68]  Qs tile
    float* s_k  = s_q + 64 * 68;    // [64][66]  Ks chunk
    float* s_v  = s_k + 64 * 66;    // [64][68]  V chunk
    float* s_p  = s_v + 64 * 68;    // [64][138] duplicated probabilities
    float* s_sk = s_p + 64 * 138;   // [64]

    const int t    = threadIdx.x;
    const int lane = t & 31;
    const int w    = t >> 5;
    const int b    = blockIdx.y;
    const int q0   = blockIdx.x * 64;

    const float* Qs = g_Qs + (size_t)b * NSEQ * 64;
    const float* Ks = g_Ks + (size_t)b * NSEQ * 64;
    const float* Vb = V    + (size_t)b * NSEQ * 64;

    for (int idx = t; idx < 64 * 16; idx += 256) {
        int r = idx >> 4, c = (idx & 15) * 4;
        *(float4*)(s_q + r * 68 + c) = *(const float4*)(Qs + (size_t)(q0 + r) * 64 + c);
    }

    float sqv[8], m[8], l[8], accx[8], accy[8];
#pragma unroll
    for (int j = 0; j < 8; j++) {
        sqv[j]  = g_sq[b * NSEQ + q0 + w * 8 + j];
        m[j]    = 1e30f;
        l[j]    = 0.f;
        accx[j] = 0.f;
        accy[j] = 0.f;
    }

    const int k0 = lane, k1 = lane + 32;

    for (int kc = 0; kc < NSEQ / 64; kc++) {
        __syncthreads();   // previous chunk fully consumed
        const int kb = kc * 64;
        for (int idx = t; idx < 64 * 16; idx += 256) {
            int r = idx >> 4, c = (idx & 15) * 4;
            float4 kv = *(const float4*)(Ks + (size_t)(kb + r) * 64 + c);
            *(float2*)(s_k + r * 66 + c)     = make_float2(kv.x, kv.y);
            *(float2*)(s_k + r * 66 + c + 2) = make_float2(kv.z, kv.w);
            *(float4*)(s_v + r * 68 + c) = *(const float4*)(Vb + (size_t)(kb + r) * 64 + c);
        }
        if (t < 64) s_sk[t] = g_sk[b * NSEQ + kb + t];
        __syncthreads();

        // ---- scores: sum_d min(Ks,Qs) for (2 k) x (8 q), packed accumulate ----
        float t0x[8], t0y[8], t1x[8], t1y[8];
#pragma unroll
        for (int j = 0; j < 8; j++) { t0x[j] = t0y[j] = t1x[j] = t1y[j] = 0.f; }

#pragma unroll 4
        for (int d = 0; d < 64; d += 2) {
            float2 a0 = *(const float2*)(s_k + k0 * 66 + d);
            float2 a1 = *(const float2*)(s_k + k1 * 66 + d);
#pragma unroll
            for (int j = 0; j < 8; j++) {
                float2 qv = *(const float2*)(s_q + (w * 8 + j) * 68 + d);
                addx2(t0x[j], t0y[j], fminf(a0.x, qv.x), fminf(a0.y, qv.y));
                addx2(t1x[j], t1y[j], fminf(a1.x, qv.x), fminf(a1.y, qv.y));
            }
        }

        const float skk0 = s_sk[k0];
        const float skk1 = s_sk[k1];
        float p0[8], p1[8];
#pragma unroll
        for (int j = 0; j < 8; j++) {
            float s0 = skk0 + sqv[j] - 2.f * (t0x[j] + t0y[j]);
            float s1 = skk1 + sqv[j] - 2.f * (t1x[j] + t1y[j]);
            float c  = fminf(s0, s1);
#pragma unroll
            for (int off = 16; off >= 1; off >>= 1)
                c = fminf(c, __shfl_xor_sync(0xffffffffu, c, off));
            float mn    = fminf(m[j], c);
            float alpha = __expf(0.5f * (mn - m[j]) * (mn + m[j]));
            m[j]  = mn;
            p0[j] = __expf(0.5f * (mn - s0) * (mn + s0));
            p1[j] = __expf(0.5f * (mn - s1) * (mn + s1));
            float r = p0[j] + p1[j];
#pragma unroll
            for (int off = 16; off >= 1; off >>= 1)
                r += __shfl_xor_sync(0xffffffffu, r, off);
            l[j]    = l[j] * alpha + r;
            accx[j] *= alpha;
            accy[j] *= alpha;
        }

        // stash duplicated p (warp-private column pairs 16w+2j)
#pragma unroll
        for (int j = 0; j < 8; j++) {
            s_p[k0 * 138 + 16 * w + 2 * j]     = p0[j];
            s_p[k0 * 138 + 16 * w + 2 * j + 1] = p0[j];
            s_p[k1 * 138 + 16 * w + 2 * j]     = p1[j];
            s_p[k1 * 138 + 16 * w + 2 * j + 1] = p1[j];
        }
        __syncwarp();

        // ---- AV: {accx,accy}[j] += {p,p} * {v.x,v.y} (one FFMA2 per (k,j)) ----
#pragma unroll 2
        for (int k = 0; k < 64; k++) {
            float2 v = *(const float2*)(s_v + k * 68 + 2 * lane);
#pragma unroll
            for (int j = 0; j < 8; j++) {
                float2 pp = *(const float2*)(s_p + k * 138 + 16 * w + 2 * j);
                fmax2(accx[j], accy[j], pp.x, pp.y, v.x, v.y);
            }
        }
    }

    // epilogue: out = (acc / l) * Wo
#pragma unroll
    for (int j = 0; j < 8; j++) {
        int q = q0 + w * 8 + j;
        float inv = 1.0f / l[j];
        size_t off = ((size_t)b * NSEQ + q) * 64 + 2 * lane;
        float2 wv = *(const float2*)(g_Wo + off);
        float2 o;
        o.x = accx[j] * inv * wv.x;
        o.y = accy[j] * inv * wv.y;
        *(float2*)(out + off) = o;
    }
}

// ---------------------------------------------------------------------------
extern "C" void kernel_launch(void* const* d_in, const int* in_sizes, int n_in,
                              void* d_out, int out_size)
{
    (void)in_sizes; (void)n_in; (void)out_size;
    const float* KEY   = (const float*)d_in[0];
    const float* VALUE = (const float*)d_in[1];
    const float* QUERY = (const float*)d_in[2];
    const float* W1w = (const float*)d_in[3],  *W1b = (const float*)d_in[4];
    const float* W2w = (const float*)d_in[5],  *W2b = (const float*)d_in[6];
    const float* W3w = (const float*)d_in[7],  *W3b = (const float*)d_in[8];
    const float* O1w = (const float*)d_in[9],  *O1b = (const float*)d_in[10];
    const float* O2w = (const float*)d_in[11], *O2b = (const float*)d_in[12];
    const float* O3w = (const float*)d_in[13], *O3b = (const float*)d_in[14];

    cudaFuncSetAttribute(mlp_kernel, cudaFuncAttributeMaxDynamicSharedMemorySize,
                         MLP_SMEM_FLOATS * sizeof(float));
    cudaFuncSetAttribute(attn_kernel, cudaFuncAttributeMaxDynamicSharedMemorySize,
                         ATT_SMEM_FLOATS * sizeof(float));

    dim3 mlp_grid(NROWS / 32, 3);
    mlp_kernel<<<mlp_grid, 256, MLP_SMEM_FLOATS * sizeof(float)>>>(
        KEY, QUERY, W1w, W1b, W2w, W2b, W3w, W3b,
        O1w, O1b, O2w, O2b, O3w, O3b);

    dim3 att_grid(NSEQ / 64, NB);
    attn_kernel<<<att_grid, 256, ATT_SMEM_FLOATS * sizeof(float)>>>(
        VALUE, (float*)d_out);
}